// round 5
// baseline (speedup 1.0000x reference)
#include <cuda_runtime.h>
#include <cstdint>
#include <cstddef>

#define B_ 4
#define L_ 512
#define D_ 256
#define H_ 128

// ---------------- scratch (device globals; no runtime allocation) ----------------
__device__ float g_own [B_*L_*H_];      // [2048,128]
__device__ float g_comp[B_*L_*H_];      // [2048,128]
__device__ float g_cat [B_*L_*2*D_];    // [2048,512]  concat(v, C)
__device__ float g_gate[B_*L_*2*D_];    // [2048,512]  gated input
__device__ float g_xpf [B_*L_*3*H_];    // [2048,384]
__device__ float g_xpb [B_*L_*3*H_];    // [2048,384]

// ---------------- helpers ----------------
__device__ __forceinline__ float tanh_fast(float x) {
    float y; asm("tanh.approx.f32 %0, %1;" : "=f"(y) : "f"(x)); return y;
}
__device__ __forceinline__ float sigmoid_fast(float x) {
    return __fdividef(1.f, 1.f + __expf(-x));
}
__device__ __forceinline__ unsigned long long pack2f(float a, float b) {
    unsigned long long r; asm("mov.b64 %0, {%1, %2};" : "=l"(r) : "f"(a), "f"(b)); return r;
}
__device__ __forceinline__ unsigned long long fma2f(unsigned long long a, unsigned long long b, unsigned long long c) {
    unsigned long long d; asm("fma.rn.f32x2 %0, %1, %2, %3;" : "=l"(d) : "l"(a), "l"(b), "l"(c)); return d;
}
__device__ __forceinline__ float2 unpack2f(unsigned long long a) {
    float x, y; asm("mov.b64 {%0, %1}, %2;" : "=f"(x), "=f"(y) : "l"(a));
    return make_float2(x, y);
}

// ---------------- generic tiled GEMM: C[m,n] = act(A[m,:K] . W[n,:K] + bias[n]) ----------------
// EPI 0: +bias.  EPI 1: sigmoid(acc+bias) * mul[m,n]   (gating; N == K)
template<int EPI>
__global__ void __launch_bounds__(256) gemm_kernel(
    const float* __restrict__ A, const float* __restrict__ W,
    const float* __restrict__ bias, const float* __restrict__ mul,
    float* __restrict__ C, int M, int N, int K)
{
    __shared__ float As[16][68];
    __shared__ float Ws[16][68];
    const int m0 = blockIdx.y * 64, n0 = blockIdx.x * 64;
    const int tid = threadIdx.x;
    const int kq = tid & 3, li = tid >> 2;     // loader mapping
    const int ty = tid >> 4, tx = tid & 15;    // compute mapping: 4x4 per thread
    float acc[4][4] = {};
    for (int k0 = 0; k0 < K; k0 += 16) {
        float4 av = *(const float4*)&A[(size_t)(m0 + li) * K + k0 + kq * 4];
        float4 wv = *(const float4*)&W[(size_t)(n0 + li) * K + k0 + kq * 4];
        __syncthreads();
        As[kq*4+0][li] = av.x; As[kq*4+1][li] = av.y; As[kq*4+2][li] = av.z; As[kq*4+3][li] = av.w;
        Ws[kq*4+0][li] = wv.x; Ws[kq*4+1][li] = wv.y; Ws[kq*4+2][li] = wv.z; Ws[kq*4+3][li] = wv.w;
        __syncthreads();
        #pragma unroll
        for (int kk = 0; kk < 16; kk++) {
            float4 a4 = *(const float4*)&As[kk][ty * 4];
            float4 w4 = *(const float4*)&Ws[kk][tx * 4];
            float aa[4] = {a4.x, a4.y, a4.z, a4.w};
            float ww[4] = {w4.x, w4.y, w4.z, w4.w};
            #pragma unroll
            for (int i = 0; i < 4; i++)
                #pragma unroll
                for (int j = 0; j < 4; j++) acc[i][j] += aa[i] * ww[j];
        }
    }
    #pragma unroll
    for (int i = 0; i < 4; i++) {
        int m = m0 + ty * 4 + i;
        float4 r;
        float* rv = (float*)&r;
        #pragma unroll
        for (int j = 0; j < 4; j++) {
            int n = n0 + tx * 4 + j;
            float val = acc[i][j] + bias[n];
            if (EPI == 1) val = sigmoid_fast(val) * mul[(size_t)m * N + n];
            rv[j] = val;
        }
        *(float4*)&C[(size_t)m * N + n0 + tx * 4] = r;
    }
}

// ---------------- attention: scores(tanh) -> softmax -> context, writes concat(v,C) ----------------
// grid (L/8, B), 256 threads. warp w owns query row q0+w.
__global__ void __launch_bounds__(256) attn_kernel(
    const float* __restrict__ v, const float* __restrict__ own,
    const float* __restrict__ comp, const float* __restrict__ va,
    const int* __restrict__ lengths, float* __restrict__ cat)
{
    __shared__ float own_s[8 * 128];
    __shared__ float va_s[128];
    __shared__ float scores[8 * 512];
    __shared__ __align__(16) float tile[32 * 132];   // union: comp tile (32x132) / v tile (16x256)
    const int b  = blockIdx.y;
    const int q0 = blockIdx.x * 8;
    const int tid = threadIdx.x;
    const int len = lengths[b];
    const size_t base = (size_t)b * L_;

    for (int i = tid; i < (8 * 128) / 4; i += 256)
        ((float4*)own_s)[i] = ((const float4*)(own + (base + q0) * H_))[i];
    if (tid < 128) va_s[tid] = va[tid];

    const int klane = tid & 31, qw = tid >> 5;

    // ---- pass 1: scores[q, k] = sum_h va[h] * tanh(own[q,h] + comp[k,h]) ----
    for (int kt = 0; kt < 16; kt++) {
        __syncthreads();
        for (int i = tid; i < 1024; i += 256) {              // 32 rows x 32 float4
            int kk = i >> 5, hq = i & 31;
            float4 cv = *(const float4*)&comp[(base + kt * 32 + kk) * H_ + hq * 4];
            *(float4*)&tile[kk * 132 + hq * 4] = cv;
        }
        __syncthreads();
        const float* orow = own_s + qw * 128;
        const float* crow = tile + klane * 132;
        float s = 0.f;
        #pragma unroll
        for (int h = 0; h < 128; h += 4) {
            float4 ov = *(const float4*)&orow[h];
            float4 cv = *(const float4*)&crow[h];
            float4 vv = *(const float4*)&va_s[h];
            s += vv.x * tanh_fast(ov.x + cv.x);
            s += vv.y * tanh_fast(ov.y + cv.y);
            s += vv.z * tanh_fast(ov.z + cv.z);
            s += vv.w * tanh_fast(ov.w + cv.w);
        }
        scores[qw * 512 + kt * 32 + klane] = s;
    }
    __syncthreads();

    // ---- softmax over k (masked at k >= len); warp qw owns row qw ----
    {
        float* row = scores + qw * 512;
        float sv[16];
        float mx = -3.0e38f;
        #pragma unroll
        for (int i = 0; i < 16; i++) {
            int k = klane + i * 32;
            sv[i] = (k < len) ? row[k] : -3.0e38f;
            mx = fmaxf(mx, sv[i]);
        }
        #pragma unroll
        for (int off = 16; off; off >>= 1) mx = fmaxf(mx, __shfl_xor_sync(0xffffffffu, mx, off));
        float sum = 0.f;
        #pragma unroll
        for (int i = 0; i < 16; i++) {
            int k = klane + i * 32;
            float e = (k < len) ? __expf(sv[i] - mx) : 0.f;
            sv[i] = e; sum += e;
        }
        #pragma unroll
        for (int off = 16; off; off >>= 1) sum += __shfl_xor_sync(0xffffffffu, sum, off);
        float inv = __fdividef(1.f, sum);
        #pragma unroll
        for (int i = 0; i < 16; i++) row[klane + i * 32] = sv[i] * inv;
    }
    __syncthreads();

    // ---- pass 2: C[q, d] = sum_k attn[q,k] * v[k,d]; thread owns (q=qw, 8 d's) ----
    float acc[8] = {};
    const int dg = tid & 31;
    for (int kt = 0; kt < 32; kt++) {
        __syncthreads();
        for (int i = tid; i < 1024; i += 256) {              // 16 rows x 64 float4
            int kk = i >> 6, dq = i & 63;
            *(float4*)&tile[kk * 256 + dq * 4] = *(const float4*)&v[(base + kt * 16 + kk) * D_ + dq * 4];
        }
        __syncthreads();
        #pragma unroll 4
        for (int kk = 0; kk < 16; kk++) {
            float a = scores[qw * 512 + kt * 16 + kk];
            float4 lo = *(const float4*)&tile[kk * 256 + dg * 4];
            float4 hi = *(const float4*)&tile[kk * 256 + 128 + dg * 4];
            acc[0] += a * lo.x; acc[1] += a * lo.y; acc[2] += a * lo.z; acc[3] += a * lo.w;
            acc[4] += a * hi.x; acc[5] += a * hi.y; acc[6] += a * hi.z; acc[7] += a * hi.w;
        }
    }
    {
        size_t m = base + q0 + qw;
        float4 o1 = make_float4(acc[0], acc[1], acc[2], acc[3]);
        float4 o2 = make_float4(acc[4], acc[5], acc[6], acc[7]);
        *(float4*)&cat[m * 512 + 256 + dg * 4] = o1;
        *(float4*)&cat[m * 512 + 384 + dg * 4] = o2;
    }
    // copy v into cat[:, 0:256]
    for (int i = tid; i < 512; i += 256) {
        int qq = i >> 6, dq = i & 63;
        size_t m = base + q0 + qq;
        *(float4*)&cat[m * 512 + dq * 4] = *(const float4*)&v[m * D_ + dq * 4];
    }
}

// ---------------- GRU recurrence: one CTA per (batch, direction); w_hh rows in registers ----------------
__global__ void __launch_bounds__(384, 1) gru_kernel(
    const float* __restrict__ xpf, const float* __restrict__ xpb,
    const float* __restrict__ whhf, const float* __restrict__ whhb,
    const float* __restrict__ bhhf, const float* __restrict__ bhhb,
    const int* __restrict__ lengths, float* __restrict__ out)
{
    const int b   = blockIdx.x & 3;
    const int dir = blockIdx.x >> 2;
    const float* xp  = dir ? xpb  : xpf;
    const float* whh = dir ? whhb : whhf;
    const float* bhh = dir ? bhhb : bhhf;
    const int o = threadIdx.x;           // 0..383 : output index of hp
    const int len = lengths[b];

    __shared__ __align__(16) float h_s[128];
    __shared__ float hp_s[384];
    __shared__ float xp_s[384];

    // w_hh row of this output, packed into f32x2 registers (128 floats -> 64 u64 regs)
    unsigned long long w2[64];
    {
        const float4* wr = (const float4*)(whh + (size_t)o * 128);
        #pragma unroll
        for (int j = 0; j < 32; j++) {
            float4 t = wr[j];
            w2[2 * j]     = pack2f(t.x, t.y);
            w2[2 * j + 1] = pack2f(t.z, t.w);
        }
    }
    const float bo = bhh[o];
    if (o < 128) h_s[o] = 0.f;
    __syncthreads();

    const size_t xbase = (size_t)b * L_ * 384;
    const size_t obase = (size_t)b * L_ * 256 + (size_t)dir * 128;

    for (int step = 0; step < L_; step++) {
        const int t = dir ? (L_ - 1 - step) : step;
        const float xv = xp[xbase + (size_t)t * 384 + o];   // issued early, hidden under matvec

        unsigned long long a0 = 0ull, a1 = 0ull, a2 = 0ull, a3 = 0ull;
        const ulonglong2* h4 = (const ulonglong2*)h_s;
        #pragma unroll
        for (int j = 0; j < 16; j++) {
            ulonglong2 hA = h4[2 * j];
            ulonglong2 hB = h4[2 * j + 1];
            a0 = fma2f(w2[4 * j + 0], hA.x, a0);
            a1 = fma2f(w2[4 * j + 1], hA.y, a1);
            a2 = fma2f(w2[4 * j + 2], hB.x, a2);
            a3 = fma2f(w2[4 * j + 3], hB.y, a3);
        }
        float2 f0 = unpack2f(a0), f1 = unpack2f(a1), f2 = unpack2f(a2), f3 = unpack2f(a3);
        float hp = bo + ((f0.x + f0.y) + (f1.x + f1.y)) + ((f2.x + f2.y) + (f3.x + f3.y));
        hp_s[o] = hp;
        xp_s[o] = xv;
        __syncthreads();

        if (o < 128) {
            float r = sigmoid_fast(xp_s[o]       + hp_s[o]);
            float z = sigmoid_fast(xp_s[128 + o] + hp_s[128 + o]);
            float n = tanh_fast  (xp_s[256 + o] + r * hp_s[256 + o]);
            float hn = (1.f - z) * n + z * h_s[o];
            bool valid = (t < len);
            out[obase + (size_t)t * 256 + o] = valid ? hn : 0.f;
            if (valid) h_s[o] = hn;
        }
        __syncthreads();
    }
}

// ---------------- launch ----------------
extern "C" void kernel_launch(void* const* d_in, const int* in_sizes, int n_in,
                              void* d_out, int out_size)
{
    (void)in_sizes; (void)n_in; (void)out_size;
    const float* v       = (const float*)d_in[0];
    const int*   lengths = (const int*)  d_in[1];
    // d_in[2] = p_mask (bool, unknown width) — recomputed from lengths, unused.
    const float* own_W   = (const float*)d_in[3];
    const float* own_b   = (const float*)d_in[4];
    const float* comp_W  = (const float*)d_in[5];
    const float* comp_b  = (const float*)d_in[6];
    const float* v_attn  = (const float*)d_in[7];
    const float* gate_W  = (const float*)d_in[8];
    const float* gate_b  = (const float*)d_in[9];
    const float* w_ih_f  = (const float*)d_in[10];
    const float* w_hh_f  = (const float*)d_in[11];
    const float* b_ih_f  = (const float*)d_in[12];
    const float* b_hh_f  = (const float*)d_in[13];
    const float* w_ih_b  = (const float*)d_in[14];
    const float* w_hh_b  = (const float*)d_in[15];
    const float* b_ih_b  = (const float*)d_in[16];
    const float* b_hh_b  = (const float*)d_in[17];
    float* out = (float*)d_out;

    float *p_own, *p_comp, *p_cat, *p_g, *p_xpf, *p_xpb;
    cudaGetSymbolAddress((void**)&p_own,  g_own);
    cudaGetSymbolAddress((void**)&p_comp, g_comp);
    cudaGetSymbolAddress((void**)&p_cat,  g_cat);
    cudaGetSymbolAddress((void**)&p_g,    g_gate);
    cudaGetSymbolAddress((void**)&p_xpf,  g_xpf);
    cudaGetSymbolAddress((void**)&p_xpb,  g_xpb);

    const int M = B_ * L_;  // 2048

    // own / comp projections: [2048,256] x [128,256]^T
    gemm_kernel<0><<<dim3(128 / 64, M / 64), 256>>>(v, own_W,  own_b,  nullptr, p_own,  M, 128, 256);
    gemm_kernel<0><<<dim3(128 / 64, M / 64), 256>>>(v, comp_W, comp_b, nullptr, p_comp, M, 128, 256);

    // attention + context -> concat(v, C)
    attn_kernel<<<dim3(L_ / 8, B_), 256>>>(v, p_own, p_comp, v_attn, lengths, p_cat);

    // gating: g = sigmoid(cat @ gate_W^T + b) * cat
    gemm_kernel<1><<<dim3(512 / 64, M / 64), 256>>>(p_cat, gate_W, gate_b, p_cat, p_g, M, 512, 512);

    // GRU input projections (both directions)
    gemm_kernel<0><<<dim3(384 / 64, M / 64), 256>>>(p_g, w_ih_f, b_ih_f, nullptr, p_xpf, M, 384, 512);
    gemm_kernel<0><<<dim3(384 / 64, M / 64), 256>>>(p_g, w_ih_b, b_ih_b, nullptr, p_xpb, M, 384, 512);

    // sequential recurrence: 8 CTAs = 4 batches x 2 directions
    gru_kernel<<<8, 384>>>(p_xpf, p_xpb, w_hh_f, w_hh_b, b_hh_f, b_hh_b, lengths, out);
}

// round 8
// speedup vs baseline: 1.1373x; 1.1373x over previous
#include <cuda_runtime.h>
#include <cstdint>
#include <cstddef>

#define B_ 4
#define L_ 512
#define D_ 256
#define H_ 128

// ---------------- scratch (device globals; no runtime allocation) ----------------
__device__ float g_own [B_*L_*H_];      // [2048,128]
__device__ float g_comp[B_*L_*H_];      // [2048,128]
__device__ float g_cat [B_*L_*2*D_];    // [2048,512]  concat(v, C)
__device__ float g_gate[B_*L_*2*D_];    // [2048,512]  gated input
__device__ float g_xpf [B_*L_*3*H_];    // [2048,384]
__device__ float g_xpb [B_*L_*3*H_];    // [2048,384]

// ---------------- helpers ----------------
__device__ __forceinline__ float tanh_fast(float x) {
    float y; asm("tanh.approx.f32 %0, %1;" : "=f"(y) : "f"(x)); return y;
}
// sigmoid(x) = 0.5*tanh(0.5x) + 0.5  -> single MUFU on the critical path
__device__ __forceinline__ float sigmoid_fast(float x) {
    return fmaf(0.5f, tanh_fast(0.5f * x), 0.5f);
}
__device__ __forceinline__ unsigned long long pack2f(float a, float b) {
    unsigned long long r; asm("mov.b64 %0, {%1, %2};" : "=l"(r) : "f"(a), "f"(b)); return r;
}
__device__ __forceinline__ unsigned long long fma2f(unsigned long long a, unsigned long long b, unsigned long long c) {
    unsigned long long d; asm("fma.rn.f32x2 %0, %1, %2, %3;" : "=l"(d) : "l"(a), "l"(b), "l"(c)); return d;
}
__device__ __forceinline__ unsigned long long add2f(unsigned long long a, unsigned long long b) {
    unsigned long long d; asm("add.rn.f32x2 %0, %1, %2;" : "=l"(d) : "l"(a), "l"(b)); return d;
}
__device__ __forceinline__ float2 unpack2f(unsigned long long a) {
    float x, y; asm("mov.b64 {%0, %1}, %2;" : "=f"(x), "=f"(y) : "l"(a));
    return make_float2(x, y);
}

// ---------------- packed-f32x2 tiled GEMM: C[m,n] = act(A[m,:K] . W[n,:K] + bias[n]) ----
// 64x64 tile, 256 threads, 4x4 per thread (as 4x2 f32x2 accumulators), double-buffered.
// A values stored DUPLICATED into smem (u64 with both halves equal) so inner loop is
// pure fma.rn.f32x2 (rt_SMSP=2 per 2 FMAs -> 2x scalar-FFMA throughput).
// blockIdx.z selects weight/bias/output set (fused twin launches).
// EPI 0: +bias.  EPI 1: sigmoid(acc+bias) * mul[m,n]   (gating; N == K)
template<int EPI>
__global__ void __launch_bounds__(256) gemm2_kernel(
    const float* __restrict__ A,
    const float* __restrict__ W0, const float* __restrict__ W1,
    const float* __restrict__ bias0, const float* __restrict__ bias1,
    const float* __restrict__ mul,
    float* __restrict__ C0, float* __restrict__ C1,
    int M, int N, int K)
{
    __shared__ __align__(16) unsigned long long As2[2][16][66]; // dup'd A, padded rows
    __shared__ __align__(16) float Ws[2][16][68];               // W tile, padded rows

    const float* W    = blockIdx.z ? W1 : W0;
    const float* bias = blockIdx.z ? bias1 : bias0;
    float*       C    = blockIdx.z ? C1 : C0;

    const int m0 = blockIdx.y * 64, n0 = blockIdx.x * 64;
    const int tid = threadIdx.x;
    const int kq = tid & 3, li = tid >> 2;     // loader mapping: 64 rows x 4 k-quads
    const int ty = tid >> 4, tx = tid & 15;    // compute mapping
    const int KT = K >> 4;

    const float* Arow = A + (size_t)(m0 + li) * K + kq * 4;
    const float* Wrow = W + (size_t)(n0 + li) * K + kq * 4;

    // prologue: tile 0
    {
        float4 av = *(const float4*)Arow;
        float4 wv = *(const float4*)Wrow;
        As2[0][kq*4+0][li] = pack2f(av.x, av.x);
        As2[0][kq*4+1][li] = pack2f(av.y, av.y);
        As2[0][kq*4+2][li] = pack2f(av.z, av.z);
        As2[0][kq*4+3][li] = pack2f(av.w, av.w);
        Ws[0][kq*4+0][li] = wv.x; Ws[0][kq*4+1][li] = wv.y;
        Ws[0][kq*4+2][li] = wv.z; Ws[0][kq*4+3][li] = wv.w;
    }
    __syncthreads();

    unsigned long long acc[4][2];
    #pragma unroll
    for (int i = 0; i < 4; i++) { acc[i][0] = 0ull; acc[i][1] = 0ull; }

    int cur = 0;
    for (int kt = 0; kt < KT; kt++) {
        float4 av, wv;
        const bool more = (kt + 1 < KT);
        if (more) {
            av = *(const float4*)(Arow + (kt + 1) * 16);
            wv = *(const float4*)(Wrow + (kt + 1) * 16);
        }
        #pragma unroll
        for (int kk = 0; kk < 16; kk++) {
            ulonglong2 aA = *(const ulonglong2*)&As2[cur][kk][ty * 4];
            ulonglong2 aB = *(const ulonglong2*)&As2[cur][kk][ty * 4 + 2];
            ulonglong2 wp = *(const ulonglong2*)&Ws[cur][kk][tx * 4];
            acc[0][0] = fma2f(aA.x, wp.x, acc[0][0]);
            acc[0][1] = fma2f(aA.x, wp.y, acc[0][1]);
            acc[1][0] = fma2f(aA.y, wp.x, acc[1][0]);
            acc[1][1] = fma2f(aA.y, wp.y, acc[1][1]);
            acc[2][0] = fma2f(aB.x, wp.x, acc[2][0]);
            acc[2][1] = fma2f(aB.x, wp.y, acc[2][1]);
            acc[3][0] = fma2f(aB.y, wp.x, acc[3][0]);
            acc[3][1] = fma2f(aB.y, wp.y, acc[3][1]);
        }
        if (more) {
            int nb = cur ^ 1;
            As2[nb][kq*4+0][li] = pack2f(av.x, av.x);
            As2[nb][kq*4+1][li] = pack2f(av.y, av.y);
            As2[nb][kq*4+2][li] = pack2f(av.z, av.z);
            As2[nb][kq*4+3][li] = pack2f(av.w, av.w);
            Ws[nb][kq*4+0][li] = wv.x; Ws[nb][kq*4+1][li] = wv.y;
            Ws[nb][kq*4+2][li] = wv.z; Ws[nb][kq*4+3][li] = wv.w;
            __syncthreads();
            cur = nb;
        }
    }

    #pragma unroll
    for (int i = 0; i < 4; i++) {
        int m = m0 + ty * 4 + i;
        float2 p0 = unpack2f(acc[i][0]);
        float2 p1 = unpack2f(acc[i][1]);
        float vals[4] = {p0.x, p0.y, p1.x, p1.y};
        float4 r;
        float* rv = (float*)&r;
        #pragma unroll
        for (int j = 0; j < 4; j++) {
            int n = n0 + tx * 4 + j;
            float val = vals[j] + bias[n];
            if (EPI == 1) val = sigmoid_fast(val) * mul[(size_t)m * N + n];
            rv[j] = val;
        }
        *(float4*)&C[(size_t)m * N + n0 + tx * 4] = r;
    }
}

// ---------------- attention: scores(tanh) -> softmax -> context, writes concat(v,C) ----------------
// grid (L/8, B), 256 threads. warp w owns query row q0+w. Key tiles beyond len skipped.
__global__ void __launch_bounds__(256) attn_kernel(
    const float* __restrict__ v, const float* __restrict__ own,
    const float* __restrict__ comp, const float* __restrict__ va,
    const int* __restrict__ lengths, float* __restrict__ cat)
{
    __shared__ float own_s[8 * 128];
    __shared__ float va_s[128];
    __shared__ float scores[8 * 512];
    __shared__ __align__(16) float tile[32 * 132];   // union: comp tile (32x132) / v tile (16x256)
    const int b  = blockIdx.y;
    const int q0 = blockIdx.x * 8;
    const int tid = threadIdx.x;
    const int len = lengths[b];
    const size_t base = (size_t)b * L_;

    for (int i = tid; i < (8 * 128) / 4; i += 256)
        ((float4*)own_s)[i] = ((const float4*)(own + (base + q0) * H_))[i];
    if (tid < 128) va_s[tid] = va[tid];

    const int klane = tid & 31, qw = tid >> 5;

    // ---- pass 1: scores[q, k] = sum_h va[h] * tanh(own[q,h] + comp[k,h]); only k-tiles < len ----
    const int kt1 = (len + 31) >> 5;
    for (int kt = 0; kt < kt1; kt++) {
        __syncthreads();
        for (int i = tid; i < 1024; i += 256) {              // 32 rows x 32 float4
            int kk = i >> 5, hq = i & 31;
            float4 cv = *(const float4*)&comp[(base + kt * 32 + kk) * H_ + hq * 4];
            *(float4*)&tile[kk * 132 + hq * 4] = cv;
        }
        __syncthreads();
        const float* orow = own_s + qw * 128;
        const float* crow = tile + klane * 132;
        float s = 0.f;
        #pragma unroll
        for (int h = 0; h < 128; h += 4) {
            float4 ov = *(const float4*)&orow[h];
            float4 cv = *(const float4*)&crow[h];
            float4 vv = *(const float4*)&va_s[h];
            s += vv.x * tanh_fast(ov.x + cv.x);
            s += vv.y * tanh_fast(ov.y + cv.y);
            s += vv.z * tanh_fast(ov.z + cv.z);
            s += vv.w * tanh_fast(ov.w + cv.w);
        }
        scores[qw * 512 + kt * 32 + klane] = s;
    }
    __syncthreads();

    // ---- softmax over k (masked at k >= len); warp qw owns row qw ----
    {
        float* row = scores + qw * 512;
        float sv[16];
        float mx = -3.0e38f;
        #pragma unroll
        for (int i = 0; i < 16; i++) {
            int k = klane + i * 32;
            sv[i] = (k < len) ? row[k] : -3.0e38f;
            mx = fmaxf(mx, sv[i]);
        }
        #pragma unroll
        for (int off = 16; off; off >>= 1) mx = fmaxf(mx, __shfl_xor_sync(0xffffffffu, mx, off));
        float sum = 0.f;
        #pragma unroll
        for (int i = 0; i < 16; i++) {
            int k = klane + i * 32;
            float e = (k < len) ? __expf(sv[i] - mx) : 0.f;
            sv[i] = e; sum += e;
        }
        #pragma unroll
        for (int off = 16; off; off >>= 1) sum += __shfl_xor_sync(0xffffffffu, sum, off);
        float inv = __fdividef(1.f, sum);
        #pragma unroll
        for (int i = 0; i < 16; i++) row[klane + i * 32] = sv[i] * inv;
    }
    __syncthreads();

    // ---- pass 2: C[q, d] = sum_k attn[q,k] * v[k,d]; only k-tiles < len (attn==0 beyond) ----
    float acc[8] = {};
    const int dg = tid & 31;
    const int kt2 = (len + 15) >> 4;
    for (int kt = 0; kt < kt2; kt++) {
        __syncthreads();
        for (int i = tid; i < 1024; i += 256) {              // 16 rows x 64 float4
            int kk = i >> 6, dq = i & 63;
            *(float4*)&tile[kk * 256 + dq * 4] = *(const float4*)&v[(base + kt * 16 + kk) * D_ + dq * 4];
        }
        __syncthreads();
        #pragma unroll 4
        for (int kk = 0; kk < 16; kk++) {
            float a = scores[qw * 512 + kt * 16 + kk];
            float4 lo = *(const float4*)&tile[kk * 256 + dg * 4];
            float4 hi = *(const float4*)&tile[kk * 256 + 128 + dg * 4];
            acc[0] += a * lo.x; acc[1] += a * lo.y; acc[2] += a * lo.z; acc[3] += a * lo.w;
            acc[4] += a * hi.x; acc[5] += a * hi.y; acc[6] += a * hi.z; acc[7] += a * hi.w;
        }
    }
    {
        size_t m = base + q0 + qw;
        float4 o1 = make_float4(acc[0], acc[1], acc[2], acc[3]);
        float4 o2 = make_float4(acc[4], acc[5], acc[6], acc[7]);
        *(float4*)&cat[m * 512 + 256 + dg * 4] = o1;
        *(float4*)&cat[m * 512 + 384 + dg * 4] = o2;
    }
    // copy v into cat[:, 0:256]
    for (int i = tid; i < 512; i += 256) {
        int qq = i >> 6, dq = i & 63;
        size_t m = base + q0 + qq;
        *(float4*)&cat[m * 512 + dq * 4] = *(const float4*)&v[m * D_ + dq * 4];
    }
}

// ---------------- GRU recurrence: one CTA per (batch, direction); w_hh rows in registers ----------------
// Only `len` real steps per batch (masked region has h=0, out=0: trailing for fwd, leading for bwd);
// the invalid region is bulk zero-filled.
__global__ void __launch_bounds__(384, 1) gru_kernel(
    const float* __restrict__ xpf, const float* __restrict__ xpb,
    const float* __restrict__ whhf, const float* __restrict__ whhb,
    const float* __restrict__ bhhf, const float* __restrict__ bhhb,
    const int* __restrict__ lengths, float* __restrict__ out)
{
    const int b   = blockIdx.x & 3;
    const int dir = blockIdx.x >> 2;
    const float* xp  = dir ? xpb  : xpf;
    const float* whh = dir ? whhb : whhf;
    const float* bhh = dir ? bhhb : bhhf;
    const int o = threadIdx.x;           // 0..383 : output index of hp
    const int len = lengths[b];

    __shared__ __align__(16) float h_s[128];
    __shared__ float hp_s[384];
    __shared__ float xp_s[384];

    // w_hh row of this output, packed into f32x2 registers (128 floats -> 64 u64 regs)
    unsigned long long w2[64];
    {
        const float4* wr = (const float4*)(whh + (size_t)o * 128);
        #pragma unroll
        for (int j = 0; j < 32; j++) {
            float4 t = wr[j];
            w2[2 * j]     = pack2f(t.x, t.y);
            w2[2 * j + 1] = pack2f(t.z, t.w);
        }
    }
    const float bo = bhh[o];
    if (o < 128) h_s[o] = 0.f;

    const size_t xbase = (size_t)b * L_ * 384;
    const size_t obase = (size_t)b * L_ * 256 + (size_t)dir * 128;

    // bulk zero-fill of the invalid region [len, L)
    for (int i = o; i < (L_ - len) * 128; i += 384) {
        int t = len + (i >> 7);
        out[obase + (size_t)t * 256 + (i & 127)] = 0.f;
    }
    __syncthreads();

    for (int s = 0; s < len; s++) {
        const int t = dir ? (len - 1 - s) : s;
        const float xv = xp[xbase + (size_t)t * 384 + o];   // issued early, hidden under matvec

        // 8 accumulator chains (shallow dependency depth)
        unsigned long long a[8];
        #pragma unroll
        for (int c = 0; c < 8; c++) a[c] = 0ull;
        const ulonglong2* h4 = (const ulonglong2*)h_s;
        #pragma unroll
        for (int j = 0; j < 8; j++) {
            ulonglong2 hA = h4[4 * j];
            ulonglong2 hB = h4[4 * j + 1];
            ulonglong2 hC = h4[4 * j + 2];
            ulonglong2 hD = h4[4 * j + 3];
            a[0] = fma2f(w2[8 * j + 0], hA.x, a[0]);
            a[1] = fma2f(w2[8 * j + 1], hA.y, a[1]);
            a[2] = fma2f(w2[8 * j + 2], hB.x, a[2]);
            a[3] = fma2f(w2[8 * j + 3], hB.y, a[3]);
            a[4] = fma2f(w2[8 * j + 4], hC.x, a[4]);
            a[5] = fma2f(w2[8 * j + 5], hC.y, a[5]);
            a[6] = fma2f(w2[8 * j + 6], hD.x, a[6]);
            a[7] = fma2f(w2[8 * j + 7], hD.y, a[7]);
        }
        a[0] = add2f(a[0], a[1]); a[2] = add2f(a[2], a[3]);
        a[4] = add2f(a[4], a[5]); a[6] = add2f(a[6], a[7]);
        a[0] = add2f(a[0], a[2]); a[4] = add2f(a[4], a[6]);
        a[0] = add2f(a[0], a[4]);
        float2 f = unpack2f(a[0]);
        hp_s[o] = bo + f.x + f.y;
        xp_s[o] = xv;
        __syncthreads();

        if (o < 128) {
            float r = sigmoid_fast(xp_s[o]       + hp_s[o]);
            float z = sigmoid_fast(xp_s[128 + o] + hp_s[128 + o]);
            float n = tanh_fast  (xp_s[256 + o] + r * hp_s[256 + o]);
            float hn = (1.f - z) * n + z * h_s[o];
            out[obase + (size_t)t * 256 + o] = hn;
            h_s[o] = hn;
        }
        __syncthreads();
    }
}

// ---------------- launch ----------------
extern "C" void kernel_launch(void* const* d_in, const int* in_sizes, int n_in,
                              void* d_out, int out_size)
{
    (void)in_sizes; (void)n_in; (void)out_size;
    const float* v       = (const float*)d_in[0];
    const int*   lengths = (const int*)  d_in[1];
    // d_in[2] = p_mask (bool) — recomputed from lengths, unused.
    const float* own_W   = (const float*)d_in[3];
    const float* own_b   = (const float*)d_in[4];
    const float* comp_W  = (const float*)d_in[5];
    const float* comp_b  = (const float*)d_in[6];
    const float* v_attn  = (const float*)d_in[7];
    const float* gate_W  = (const float*)d_in[8];
    const float* gate_b  = (const float*)d_in[9];
    const float* w_ih_f  = (const float*)d_in[10];
    const float* w_hh_f  = (const float*)d_in[11];
    const float* b_ih_f  = (const float*)d_in[12];
    const float* b_hh_f  = (const float*)d_in[13];
    const float* w_ih_b  = (const float*)d_in[14];
    const float* w_hh_b  = (const float*)d_in[15];
    const float* b_ih_b  = (const float*)d_in[16];
    const float* b_hh_b  = (const float*)d_in[17];
    float* out = (float*)d_out;

    float *p_own, *p_comp, *p_cat, *p_g, *p_xpf, *p_xpb;
    cudaGetSymbolAddress((void**)&p_own,  g_own);
    cudaGetSymbolAddress((void**)&p_comp, g_comp);
    cudaGetSymbolAddress((void**)&p_cat,  g_cat);
    cudaGetSymbolAddress((void**)&p_g,    g_gate);
    cudaGetSymbolAddress((void**)&p_xpf,  g_xpf);
    cudaGetSymbolAddress((void**)&p_xpb,  g_xpb);

    const int M = B_ * L_;  // 2048

    // own + comp projections fused (z selects): [2048,256] x [128,256]^T
    gemm2_kernel<0><<<dim3(128 / 64, M / 64, 2), 256>>>(
        v, own_W, comp_W, own_b, comp_b, nullptr, p_own, p_comp, M, 128, 256);

    // attention + context -> concat(v, C)
    attn_kernel<<<dim3(L_ / 8, B_), 256>>>(v, p_own, p_comp, v_attn, lengths, p_cat);

    // gating: g = sigmoid(cat @ gate_W^T + b) * cat
    gemm2_kernel<1><<<dim3(512 / 64, M / 64, 1), 256>>>(
        p_cat, gate_W, gate_W, gate_b, gate_b, p_cat, p_g, p_g, M, 512, 512);

    // GRU input projections, both directions fused (z selects)
    gemm2_kernel<0><<<dim3(384 / 64, M / 64, 2), 256>>>(
        p_g, w_ih_f, w_ih_b, b_ih_f, b_ih_b, nullptr, p_xpf, p_xpb, M, 384, 512);

    // sequential recurrence: 8 CTAs = 4 batches x 2 directions
    gru_kernel<<<8, 384>>>(p_xpf, p_xpb, w_hh_f, w_hh_b, b_hh_f, b_hh_b, lengths, out);
}